// round 13
// baseline (speedup 1.0000x reference)
#include <cuda_runtime.h>
#include <cuda_fp16.h>
#include <cstdint>

#define N_TOK 4096
#define C_CH  256
#define C_RED 64
#define B_SZ  4

// fp16 copies of weights
__device__ __half g_wh[192 * C_CH];            // [r(Q0-63,K64-127,V128-191)][c]
__device__ __half g_wph[C_CH * C_RED];         // [c][r] 128B rows
// fp16 scratch: Q (pre-scaled by 0.125*log2e), K, V all [b][token][d], 128B rows
__device__ __half g_q[B_SZ * N_TOK * C_RED];
__device__ __half g_k[B_SZ * N_TOK * C_RED];
__device__ __half g_v[B_SZ * N_TOK * C_RED];

#define SW128(off) ((off) ^ (((off) >> 3) & 0x70))
#define SW256(off) ((off) ^ (((off) >> 4) & 0x70))

__device__ __forceinline__ uint32_t smem_u32(const void* p) {
    uint32_t a;
    asm("{ .reg .u64 t; cvta.to.shared.u64 t, %1; cvt.u32.u64 %0, t; }" : "=r"(a) : "l"(p));
    return a;
}
__device__ __forceinline__ void cp16(uint32_t dst, const void* src) {
    uint64_t g;
    asm("cvta.to.global.u64 %0, %1;" : "=l"(g) : "l"(src));
    asm volatile("cp.async.cg.shared.global [%0], [%1], 16;" :: "r"(dst), "l"(g) : "memory");
}
#define CP_COMMIT() asm volatile("cp.async.commit_group;" ::: "memory")
#define CP_WAIT0()  asm volatile("cp.async.wait_group 0;" ::: "memory")
#define CP_WAIT1()  asm volatile("cp.async.wait_group 1;" ::: "memory")

__device__ __forceinline__ void ldsm4(uint32_t (&r)[4], uint32_t addr) {
    asm volatile("ldmatrix.sync.aligned.m8n8.x4.shared.b16 {%0,%1,%2,%3}, [%4];"
        : "=r"(r[0]), "=r"(r[1]), "=r"(r[2]), "=r"(r[3]) : "r"(addr));
}
__device__ __forceinline__ void ldsm4t(uint32_t (&r)[4], uint32_t addr) {
    asm volatile("ldmatrix.sync.aligned.m8n8.x4.trans.shared.b16 {%0,%1,%2,%3}, [%4];"
        : "=r"(r[0]), "=r"(r[1]), "=r"(r[2]), "=r"(r[3]) : "r"(addr));
}
__device__ __forceinline__ void mma_f16(float* d, const uint32_t* a, uint32_t b0, uint32_t b1) {
    asm volatile(
        "mma.sync.aligned.m16n8k16.row.col.f32.f16.f16.f32 "
        "{%0,%1,%2,%3}, {%4,%5,%6,%7}, {%8,%9}, {%0,%1,%2,%3};"
        : "+f"(d[0]), "+f"(d[1]), "+f"(d[2]), "+f"(d[3])
        : "r"(a[0]), "r"(a[1]), "r"(a[2]), "r"(a[3]), "r"(b0), "r"(b1));
}
__device__ __forceinline__ uint32_t exp2_h2(uint32_t s) {
    uint32_t r;
    asm("ex2.approx.f16x2 %0, %1;" : "=r"(r) : "r"(s));
    return r;
}
__device__ __forceinline__ uint32_t packh(float lo, float hi) {
    __half2 h = __floats2half2_rn(lo, hi);
    return *(uint32_t*)&h;
}

// ---------------------------------------------------------------------------
// Convert weights only (tiny): Wqkv concat -> g_wh, Wp -> g_wph
// ---------------------------------------------------------------------------
#define NW4 (192 * C_CH / 4)
#define NP4 (C_CH * C_RED / 4)
__global__ __launch_bounds__(256) void convert_w_kernel(
    const float* __restrict__ Wq,
    const float* __restrict__ Wk,
    const float* __restrict__ Wv,
    const float* __restrict__ Wp)
{
    int i = blockIdx.x * 256 + threadIdx.x;   // grid covers NW4 + NP4 exactly
    float4 v;
    __half* dst;
    int o;
    if (i < NW4) {
        int e = i * 4;
        int r = e >> 8, c = e & 255;
        const float* W = (r < 64) ? Wq : (r < 128) ? Wk : Wv;
        v = *(const float4*)(W + (r & 63) * C_CH + c);
        dst = g_wh; o = e;
    } else {
        int e = (i - NW4) * 4;
        v = *(const float4*)(Wp + e);
        dst = g_wph; o = e;
    }
    uint2 u2;
    u2.x = packh(v.x, v.y);
    u2.y = packh(v.z, v.w);
    *(uint2*)(dst + o) = u2;
}

// ---------------------------------------------------------------------------
// Tensorized fused QKV, reads x fp32 directly (register-prefetched LDG ->
// cvt -> STS fp16).  Per CTA 128 tokens x 192 rows, K=256 in 4 chunks.
// smem: W [192][64]x2 @0/24576 (cp.async); X [64][128]x2 @49152/65536.
// ---------------------------------------------------------------------------
#define QKV_SMEM 81920
__global__ __launch_bounds__(384) void qkv_tc_kernel(const float* __restrict__ x)
{
    extern __shared__ char smem[];
    const uint32_t sb = smem_u32(smem);
    const int tid = threadIdx.x;
    const int lane = tid & 31;
    const int w = tid >> 5;
    const int n0 = blockIdx.x * 128;
    const int b  = blockIdx.y;
    const int rl = ((lane >> 3) & 1) * 8 + (lane & 7);
    const int cb = (lane >> 4) * 16;

    auto issue_w = [&](int ch) {
        const int c0 = ch * 64;
        const uint32_t WS = (ch & 1) * 24576u;
        for (int i = tid; i < 1536; i += 384) {
            int r = i >> 3, c16 = i & 7;
            cp16(sb + WS + SW128((uint32_t)r * 128 + c16 * 16),
                 g_wh + (size_t)r * C_CH + c0 + c16 * 8);
        }
        CP_COMMIT();
    };

    // x chunk: 64 channels x 128 tokens fp32.  1024 fp16-granules of 16B
    // (= 8 tokens); each needs two float4 loads.
    float4 xr[3][2];
    auto ldg_x = [&](int ch) {
        const int c0 = ch * 64;
        const float* xb = x + ((size_t)(b * C_CH) + c0) * N_TOK + n0;
        #pragma unroll
        for (int k = 0; k < 3; k++) {
            int g = tid + k * 384;
            if (g < 1024) {
                int c = g >> 4, gi = g & 15;
                const float* s = xb + (size_t)c * N_TOK + gi * 8;
                xr[k][0] = *(const float4*)s;
                xr[k][1] = *(const float4*)(s + 4);
            }
        }
    };
    auto sts_x = [&](int ch) {
        const uint32_t XS = 49152u + (ch & 1) * 16384u;
        #pragma unroll
        for (int k = 0; k < 3; k++) {
            int g = tid + k * 384;
            if (g < 1024) {
                int c = g >> 4, gi = g & 15;
                uint4 u;
                u.x = packh(xr[k][0].x, xr[k][0].y);
                u.y = packh(xr[k][0].z, xr[k][0].w);
                u.z = packh(xr[k][1].x, xr[k][1].y);
                u.w = packh(xr[k][1].z, xr[k][1].w);
                *(uint4*)(smem + XS + SW256((uint32_t)c * 256 + gi * 16)) = u;
            }
        }
    };

    ldg_x(0);
    issue_w(0);

    float acc[2][8][4] = {};
    const int mbase = (w & 3) * 32;
    const int rbase = (w >> 2) * 64;

    for (int ch = 0; ch < 4; ch++) {
        sts_x(ch);                 // stage ch&1 free: all threads past sync(ch-1)
        if (ch < 3) ldg_x(ch + 1); // prefetch next chunk into regs
        CP_WAIT0();                // W(ch) arrived
        __syncthreads();
        if (ch < 3) issue_w(ch + 1);
        const uint32_t WS = sb + (ch & 1) * 24576u;
        const uint32_t XS = sb + 49152u + (ch & 1) * 16384u;

        #pragma unroll
        for (int ks = 0; ks < 4; ks++) {
            uint32_t af[2][4];
            #pragma unroll
            for (int mt = 0; mt < 2; mt++) {
                uint32_t v[4];
                ldsm4t(v, XS + SW256((uint32_t)(ks * 16 + rl) * 256 + (mbase + mt * 16) * 2 + cb));
                af[mt][0] = v[0]; af[mt][1] = v[2]; af[mt][2] = v[1]; af[mt][3] = v[3];
            }
            #pragma unroll
            for (int nb2 = 0; nb2 < 4; nb2++) {
                uint32_t wf[4];
                ldsm4(wf, WS + SW128((uint32_t)(rbase + nb2 * 16 + rl) * 128 + ks * 32 + cb));
                #pragma unroll
                for (int mt = 0; mt < 2; mt++) {
                    mma_f16(acc[mt][2 * nb2],     af[mt], wf[0], wf[2]);
                    mma_f16(acc[mt][2 * nb2 + 1], af[mt], wf[1], wf[3]);
                }
            }
        }
    }

    // Q gets the softmax scale folded in (0.125 * log2(e))
    const float qs = (rbase == 0) ? 0.18033688011112042f : 1.0f;
    __half* garr = (w >> 2) == 0 ? g_q : (w >> 2) == 1 ? g_k : g_v;
    #pragma unroll
    for (int mt = 0; mt < 2; mt++)
        #pragma unroll
        for (int nt = 0; nt < 8; nt++) {
            int token = n0 + mbase + mt * 16 + (lane >> 2);
            int r = nt * 8 + (lane & 3) * 2;
            uint32_t v01 = packh(acc[mt][nt][0] * qs, acc[mt][nt][1] * qs);
            uint32_t v23 = packh(acc[mt][nt][2] * qs, acc[mt][nt][3] * qs);
            *(uint32_t*)&garr[((size_t)(b * N_TOK) + token) * C_RED + r] = v01;
            *(uint32_t*)&garr[((size_t)(b * N_TOK) + token + 8) * C_RED + r] = v23;
        }
}

// ---------------------------------------------------------------------------
// Fused HMMA flash attention + output projection + residual.  fp16 path.
// 3-stage KV pipeline; the two KV stages that go dead at the end are reused
// to cp.async-prefetch the residual x tile (channels 0-127).
// smem: Q 16K @0 (reused as f16 O tile); KV bufs @16384/49152/81920;
//       Wp @114688.  Total 147456.
// ---------------------------------------------------------------------------
#define ATTN_SMEM 147456
#define WP_OFF 114688
#define NKT (N_TOK / 128)
__global__ __launch_bounds__(256, 1) void attn_mma_kernel(
    const float* __restrict__ x,
    float* __restrict__ out)
{
    extern __shared__ char smem[];
    const uint32_t sb = smem_u32(smem);
    const int tid  = threadIdx.x;
    const int lane = tid & 31;
    const int w    = tid >> 5;
    const int n0   = blockIdx.x * 128;
    const int b    = blockIdx.y;
    const int rl = ((lane >> 3) & 1) * 8 + (lane & 7);
    const int cb = (lane >> 4) * 16;

    auto issue_kv = [&](int kt) {
        const int m0 = kt * 128;
        const uint32_t base = 16384u + (uint32_t)(kt % 3) * 32768u;
        for (int i = tid; i < 2048; i += 256) {
            const __half* src = (i < 1024) ? g_k : g_v;
            uint32_t off = (i < 1024) ? base : base + 16384;
            int g = i & 1023;
            int row = g >> 3, c16 = g & 7;
            cp16(sb + off + SW128((uint32_t)row * 128 + c16 * 16),
                 src + ((size_t)(b * N_TOK) + m0 + row) * C_RED + c16 * 8);
        }
        CP_COMMIT();
    };

    // Residual prefetch: half 0 -> channels [0,64) into stage 2 (@81920),
    // half 1 -> channels [64,128) into stage 0 (@16384).  Plain rows, 512B.
    auto issue_x = [&](int half) {
        const uint32_t base = half ? 16384u : 81920u;
        const float* src = x + ((size_t)(b * C_CH) + half * 64) * N_TOK + n0;
        for (int i = tid; i < 2048; i += 256) {
            int c = i >> 5, g = i & 31;
            cp16(sb + base + (uint32_t)c * 512 + g * 16,
                 src + (size_t)c * N_TOK + g * 4);
        }
        CP_COMMIT();
    };

    // prologue: Q + Wp (group 0), then KV tiles 0 and 1 (groups 1, 2)
    {
        for (int i = tid; i < 3072; i += 256) {
            if (i < 1024) {
                int row = i >> 3, c16 = i & 7;
                cp16(sb + SW128((uint32_t)row * 128 + c16 * 16),
                     g_q + ((size_t)(b * N_TOK) + n0 + row) * C_RED + c16 * 8);
            } else {
                int g = i - 1024;
                int row = g >> 3, c16 = g & 7;
                cp16(sb + WP_OFF + SW128((uint32_t)row * 128 + c16 * 16),
                     g_wph + (size_t)row * C_RED + c16 * 8);
            }
        }
        CP_COMMIT();
        issue_kv(0);
        issue_kv(1);
    }

    uint32_t qf[4][4];
    float oacc[8][4] = {};
    float l0 = 0.0f, l1 = 0.0f;

    for (int kt = 0; kt < NKT; kt++) {
        if (kt < NKT - 1) CP_WAIT1(); else CP_WAIT0();
        __syncthreads();
        if (kt + 2 < NKT) issue_kv(kt + 2);
        else issue_x(kt + 2 - NKT);   // kt=NKT-2 -> half0 (stage2), NKT-1 -> half1 (stage0)
        if (kt == 0) {
            uint32_t rowoff = (uint32_t)(w * 16 + rl) * 128 + cb;
            #pragma unroll
            for (int ks = 0; ks < 4; ks++)
                ldsm4(qf[ks], sb + SW128(rowoff + ks * 32));
        }
        const uint32_t SK = sb + 16384u + (uint32_t)(kt % 3) * 32768u;
        const uint32_t SV = SK + 16384;

        // ---- S = Q K^T (Q pre-scaled so S is the ex2 argument) ----
        float sacc[16][4];
        #pragma unroll
        for (int t = 0; t < 16; t++)
            #pragma unroll
            for (int c = 0; c < 4; c++) sacc[t][c] = 0.0f;

        #pragma unroll
        for (int nb = 0; nb < 8; nb++) {
            uint32_t tokoff = (uint32_t)(nb * 16 + rl) * 128 + cb;
            #pragma unroll
            for (int ks = 0; ks < 4; ks++) {
                uint32_t kf[4];
                ldsm4(kf, SK + SW128(tokoff + ks * 32));
                mma_f16(sacc[2 * nb],     qf[ks], kf[0], kf[2]);
                mma_f16(sacc[2 * nb + 1], qf[ks], kf[1], kf[3]);
            }
        }

        // ---- fused softmax (packed f16x2 ex2) + PV ----
        __half2 hl0 = __float2half2_rn(0.0f);
        __half2 hl1 = __float2half2_rn(0.0f);
        #pragma unroll
        for (int j = 0; j < 8; j++) {
            uint32_t pf[4];
            pf[0] = exp2_h2(packh(sacc[2 * j][0],     sacc[2 * j][1]));
            pf[1] = exp2_h2(packh(sacc[2 * j][2],     sacc[2 * j][3]));
            pf[2] = exp2_h2(packh(sacc[2 * j + 1][0], sacc[2 * j + 1][1]));
            pf[3] = exp2_h2(packh(sacc[2 * j + 1][2], sacc[2 * j + 1][3]));
            hl0 = __hadd2(hl0, __hadd2(*(__half2*)&pf[0], *(__half2*)&pf[2]));
            hl1 = __hadd2(hl1, __hadd2(*(__half2*)&pf[1], *(__half2*)&pf[3]));

            uint32_t tokoff = (uint32_t)(j * 16 + rl) * 128 + cb;
            #pragma unroll
            for (int db = 0; db < 4; db++) {
                uint32_t vf[4];
                ldsm4t(vf, SV + SW128(tokoff + db * 32));
                mma_f16(oacc[2 * db],     pf, vf[0], vf[1]);
                mma_f16(oacc[2 * db + 1], pf, vf[2], vf[3]);
            }
        }
        float2 f0 = __half22float2(hl0);
        float2 f1 = __half22float2(hl1);
        l0 += f0.x + f0.y;
        l1 += f1.x + f1.y;
    }

    // ---- normalize O, stage as f16 into smem (reuse Q region) ----
    l0 += __shfl_xor_sync(0xffffffffu, l0, 1);
    l0 += __shfl_xor_sync(0xffffffffu, l0, 2);
    l1 += __shfl_xor_sync(0xffffffffu, l1, 1);
    l1 += __shfl_xor_sync(0xffffffffu, l1, 2);
    float i0 = 1.0f / l0, i1 = 1.0f / l1;

    {
        int lr = w * 16 + (lane >> 2);
        #pragma unroll
        for (int t = 0; t < 8; t++) {
            uint32_t cbyte = (uint32_t)(t * 8 + (lane & 3) * 2) * 2;
            *(uint32_t*)(smem + SW128((uint32_t)lr * 128 + cbyte)) =
                packh(oacc[t][0] * i0, oacc[t][1] * i0);
            *(uint32_t*)(smem + SW128((uint32_t)(lr + 8) * 128 + cbyte)) =
                packh(oacc[t][2] * i1, oacc[t][3] * i1);
        }
    }
    CP_WAIT0();          // residual x halves landed
    __syncthreads();

    // ---- projection: out[c][tok] = Wp[c][r] * O[tok][r] + x ----
    const int cg = w & 3, tg = w >> 2;
    float pacc[4][8][4] = {};
    #pragma unroll
    for (int ks = 0; ks < 4; ks++) {
        uint32_t awf[4][4];
        #pragma unroll
        for (int mt = 0; mt < 4; mt++)
            ldsm4(awf[mt], sb + WP_OFF +
                  SW128((uint32_t)(cg * 64 + mt * 16 + rl) * 128 + ks * 32 + cb));
        #pragma unroll
        for (int nb = 0; nb < 4; nb++) {
            uint32_t of[4];
            ldsm4(of, sb + SW128((uint32_t)(tg * 64 + nb * 16 + rl) * 128 + ks * 32 + cb));
            #pragma unroll
            for (int mt = 0; mt < 4; mt++) {
                mma_f16(pacc[mt][2 * nb],     awf[mt], of[0], of[2]);
                mma_f16(pacc[mt][2 * nb + 1], awf[mt], of[1], of[3]);
            }
        }
    }

    // ---- epilogue: residual add + store.  cg 0/1 -> x from smem, 2/3 -> LDG ----
    #pragma unroll
    for (int mt = 0; mt < 4; mt++) {
        int c = cg * 64 + mt * 16 + (lane >> 2);
        #pragma unroll
        for (int nt = 0; nt < 8; nt++) {
            int tl = tg * 64 + nt * 8 + (lane & 3) * 2;
            size_t gi = ((size_t)(b * C_CH + c)) * N_TOK + n0 + tl;
            float2 x0, x1;
            if (cg < 2) {
                uint32_t base = (c >> 6) ? 16384u : 81920u;
                x0 = *(float2*)(smem + base + (uint32_t)(c & 63) * 512 + tl * 4);
                x1 = *(float2*)(smem + base + (uint32_t)((c & 63) + 8) * 512 + tl * 4);
            } else {
                x0 = *(const float2*)(x + gi);
                x1 = *(const float2*)(x + gi + 8 * N_TOK);
            }
            *(float2*)(out + gi) =
                make_float2(pacc[mt][nt][0] + x0.x, pacc[mt][nt][1] + x0.y);
            *(float2*)(out + gi + 8 * N_TOK) =
                make_float2(pacc[mt][nt][2] + x1.x, pacc[mt][nt][3] + x1.y);
        }
    }
}

extern "C" void kernel_launch(void* const* d_in, const int* in_sizes, int n_in,
                              void* d_out, int out_size)
{
    const float* x  = (const float*)d_in[0];
    const float* Wq = (const float*)d_in[1];
    const float* Wk = (const float*)d_in[2];
    const float* Wv = (const float*)d_in[3];
    const float* Wp = (const float*)d_in[4];
    float* out = (float*)d_out;

    cudaFuncSetAttribute(qkv_tc_kernel,   cudaFuncAttributeMaxDynamicSharedMemorySize, QKV_SMEM);
    cudaFuncSetAttribute(attn_mma_kernel, cudaFuncAttributeMaxDynamicSharedMemorySize, ATTN_SMEM);

    convert_w_kernel<<<(NW4 + NP4) / 256, 256>>>(Wq, Wk, Wv, Wp);
    qkv_tc_kernel  <<<dim3(N_TOK / 128, B_SZ), 384, QKV_SMEM>>>(x);
    attn_mma_kernel<<<dim3(N_TOK / 128, B_SZ), 256, ATTN_SMEM>>>(x, out);
}

// round 14
// speedup vs baseline: 1.0769x; 1.0769x over previous
#include <cuda_runtime.h>
#include <cuda_fp16.h>
#include <cstdint>

#define N_TOK 4096
#define C_CH  256
#define C_RED 64
#define B_SZ  4

// fp16 scratch: Q (pre-scaled by 0.125*log2e), K, V all [b][token][d], 128B rows
__device__ __half g_q[B_SZ * N_TOK * C_RED];
__device__ __half g_k[B_SZ * N_TOK * C_RED];
__device__ __half g_v[B_SZ * N_TOK * C_RED];

#define SW128(off) ((off) ^ (((off) >> 3) & 0x70))
#define SW256(off) ((off) ^ (((off) >> 4) & 0x70))

__device__ __forceinline__ uint32_t smem_u32(const void* p) {
    uint32_t a;
    asm("{ .reg .u64 t; cvta.to.shared.u64 t, %1; cvt.u32.u64 %0, t; }" : "=r"(a) : "l"(p));
    return a;
}
__device__ __forceinline__ void cp16(uint32_t dst, const void* src) {
    uint64_t g;
    asm("cvta.to.global.u64 %0, %1;" : "=l"(g) : "l"(src));
    asm volatile("cp.async.cg.shared.global [%0], [%1], 16;" :: "r"(dst), "l"(g) : "memory");
}
#define CP_COMMIT() asm volatile("cp.async.commit_group;" ::: "memory")
#define CP_WAIT0()  asm volatile("cp.async.wait_group 0;" ::: "memory")
#define CP_WAIT1()  asm volatile("cp.async.wait_group 1;" ::: "memory")

__device__ __forceinline__ void ldsm4(uint32_t (&r)[4], uint32_t addr) {
    asm volatile("ldmatrix.sync.aligned.m8n8.x4.shared.b16 {%0,%1,%2,%3}, [%4];"
        : "=r"(r[0]), "=r"(r[1]), "=r"(r[2]), "=r"(r[3]) : "r"(addr));
}
__device__ __forceinline__ void ldsm4t(uint32_t (&r)[4], uint32_t addr) {
    asm volatile("ldmatrix.sync.aligned.m8n8.x4.trans.shared.b16 {%0,%1,%2,%3}, [%4];"
        : "=r"(r[0]), "=r"(r[1]), "=r"(r[2]), "=r"(r[3]) : "r"(addr));
}
__device__ __forceinline__ void mma_f16(float* d, const uint32_t* a, uint32_t b0, uint32_t b1) {
    asm volatile(
        "mma.sync.aligned.m16n8k16.row.col.f32.f16.f16.f32 "
        "{%0,%1,%2,%3}, {%4,%5,%6,%7}, {%8,%9}, {%0,%1,%2,%3};"
        : "+f"(d[0]), "+f"(d[1]), "+f"(d[2]), "+f"(d[3])
        : "r"(a[0]), "r"(a[1]), "r"(a[2]), "r"(a[3]), "r"(b0), "r"(b1));
}
// f16 accumulator variant (S matrix): D regs are packed f16x2 pairs
__device__ __forceinline__ void mma_f16a(uint32_t* d, const uint32_t* a, uint32_t b0, uint32_t b1) {
    asm volatile(
        "mma.sync.aligned.m16n8k16.row.col.f16.f16.f16.f16 "
        "{%0,%1}, {%2,%3,%4,%5}, {%6,%7}, {%0,%1};"
        : "+r"(d[0]), "+r"(d[1])
        : "r"(a[0]), "r"(a[1]), "r"(a[2]), "r"(a[3]), "r"(b0), "r"(b1));
}
__device__ __forceinline__ uint32_t exp2_h2(uint32_t s) {
    uint32_t r;
    asm("ex2.approx.f16x2 %0, %1;" : "=r"(r) : "r"(s));
    return r;
}
__device__ __forceinline__ uint32_t packh(float lo, float hi) {
    __half2 h = __floats2half2_rn(lo, hi);
    return *(uint32_t*)&h;
}

// ---------------------------------------------------------------------------
// Tensorized fused QKV, reads x and Wq/Wk/Wv fp32 directly.
// Per CTA 128 tokens x 192 rows, K=256 in 4 chunks.
// smem: W fp16 full [192][256] as 4 chunk tiles [192][64] @ ch*24576 (96KB);
//       X fp16 [64][128] double @98304/114688.  Total 131072.
// ---------------------------------------------------------------------------
#define QKV_SMEM 131072
__global__ __launch_bounds__(384) void qkv_tc_kernel(
    const float* __restrict__ x,
    const float* __restrict__ Wq,
    const float* __restrict__ Wk,
    const float* __restrict__ Wv)
{
    extern __shared__ char smem[];
    const uint32_t sb = smem_u32(smem);
    const int tid = threadIdx.x;
    const int lane = tid & 31;
    const int w = tid >> 5;
    const int n0 = blockIdx.x * 128;
    const int b  = blockIdx.y;
    const int rl = ((lane >> 3) & 1) * 8 + (lane & 7);
    const int cb = (lane >> 4) * 16;

    // x chunk prefetch into registers (64 ch x 128 tok fp32 = 1024 16B-granules)
    float4 xr[3][2];
    auto ldg_x = [&](int ch) {
        const int c0 = ch * 64;
        const float* xb = x + ((size_t)(b * C_CH) + c0) * N_TOK + n0;
        #pragma unroll
        for (int k = 0; k < 3; k++) {
            int g = tid + k * 384;
            if (g < 1024) {
                int c = g >> 4, gi = g & 15;
                const float* s = xb + (size_t)c * N_TOK + gi * 8;
                xr[k][0] = *(const float4*)s;
                xr[k][1] = *(const float4*)(s + 4);
            }
        }
    };
    auto sts_x = [&](int ch) {
        const uint32_t XS = 98304u + (ch & 1) * 16384u;
        #pragma unroll
        for (int k = 0; k < 3; k++) {
            int g = tid + k * 384;
            if (g < 1024) {
                int c = g >> 4, gi = g & 15;
                uint4 u;
                u.x = packh(xr[k][0].x, xr[k][0].y);
                u.y = packh(xr[k][0].z, xr[k][0].w);
                u.z = packh(xr[k][1].x, xr[k][1].y);
                u.w = packh(xr[k][1].z, xr[k][1].w);
                *(uint4*)(smem + XS + SW256((uint32_t)c * 256 + gi * 16)) = u;
            }
        }
    };

    ldg_x(0);

    // Convert all Wqkv fp32 -> fp16 chunk tiles (192 rows x 32 granules of 8 cols)
    #pragma unroll 4
    for (int g = tid; g < 6144; g += 384) {
        int r = g >> 5, c8 = g & 31;
        const float* Wsrc = (r < 64 ? Wq : r < 128 ? Wk : Wv) + (r & 63) * C_CH + c8 * 8;
        float4 v0 = *(const float4*)Wsrc;
        float4 v1 = *(const float4*)(Wsrc + 4);
        uint4 u;
        u.x = packh(v0.x, v0.y);
        u.y = packh(v0.z, v0.w);
        u.z = packh(v1.x, v1.y);
        u.w = packh(v1.z, v1.w);
        *(uint4*)(smem + (uint32_t)(c8 >> 3) * 24576u +
                  SW128((uint32_t)r * 128 + (c8 & 7) * 16)) = u;
    }

    float acc[2][8][4] = {};
    const int mbase = (w & 3) * 32;
    const int rbase = (w >> 2) * 64;

    for (int ch = 0; ch < 4; ch++) {
        sts_x(ch);
        __syncthreads();           // X(ch) (and W on ch=0) visible
        if (ch < 3) ldg_x(ch + 1); // refill regs; latency hidden by compute
        const uint32_t WS = sb + (uint32_t)ch * 24576u;
        const uint32_t XS = sb + 98304u + (ch & 1) * 16384u;

        #pragma unroll
        for (int ks = 0; ks < 4; ks++) {
            uint32_t af[2][4];
            #pragma unroll
            for (int mt = 0; mt < 2; mt++) {
                uint32_t v[4];
                ldsm4t(v, XS + SW256((uint32_t)(ks * 16 + rl) * 256 + (mbase + mt * 16) * 2 + cb));
                af[mt][0] = v[0]; af[mt][1] = v[2]; af[mt][2] = v[1]; af[mt][3] = v[3];
            }
            #pragma unroll
            for (int nb2 = 0; nb2 < 4; nb2++) {
                uint32_t wf[4];
                ldsm4(wf, WS + SW128((uint32_t)(rbase + nb2 * 16 + rl) * 128 + ks * 32 + cb));
                #pragma unroll
                for (int mt = 0; mt < 2; mt++) {
                    mma_f16(acc[mt][2 * nb2],     af[mt], wf[0], wf[2]);
                    mma_f16(acc[mt][2 * nb2 + 1], af[mt], wf[1], wf[3]);
                }
            }
        }
    }

    // Q gets the softmax scale folded in (0.125 * log2(e))
    const float qs = (rbase == 0) ? 0.18033688011112042f : 1.0f;
    __half* garr = (w >> 2) == 0 ? g_q : (w >> 2) == 1 ? g_k : g_v;
    #pragma unroll
    for (int mt = 0; mt < 2; mt++)
        #pragma unroll
        for (int nt = 0; nt < 8; nt++) {
            int token = n0 + mbase + mt * 16 + (lane >> 2);
            int r = nt * 8 + (lane & 3) * 2;
            uint32_t v01 = packh(acc[mt][nt][0] * qs, acc[mt][nt][1] * qs);
            uint32_t v23 = packh(acc[mt][nt][2] * qs, acc[mt][nt][3] * qs);
            *(uint32_t*)&garr[((size_t)(b * N_TOK) + token) * C_RED + r] = v01;
            *(uint32_t*)&garr[((size_t)(b * N_TOK) + token + 8) * C_RED + r] = v23;
        }
}

// ---------------------------------------------------------------------------
// Fused HMMA flash attention + output projection + residual.  fp16 path,
// f16-accumulator S-MMA.  3-stage KV pipeline; dead stages recycled for the
// residual-x prefetch.  Wp converted fp32->fp16 in-prologue.
// smem: Q 16K @0 (reused as f16 O tile); KV bufs @16384/49152/81920;
//       Wp @114688.  Total 147456.
// ---------------------------------------------------------------------------
#define ATTN_SMEM 147456
#define WP_OFF 114688
#define NKT (N_TOK / 128)
__global__ __launch_bounds__(256, 1) void attn_mma_kernel(
    const float* __restrict__ x,
    const float* __restrict__ Wp,
    float* __restrict__ out)
{
    extern __shared__ char smem[];
    const uint32_t sb = smem_u32(smem);
    const int tid  = threadIdx.x;
    const int lane = tid & 31;
    const int w    = tid >> 5;
    const int n0   = blockIdx.x * 128;
    const int b    = blockIdx.y;
    const int rl = ((lane >> 3) & 1) * 8 + (lane & 7);
    const int cb = (lane >> 4) * 16;

    auto issue_kv = [&](int kt) {
        const int m0 = kt * 128;
        const uint32_t base = 16384u + (uint32_t)(kt % 3) * 32768u;
        for (int i = tid; i < 2048; i += 256) {
            const __half* src = (i < 1024) ? g_k : g_v;
            uint32_t off = (i < 1024) ? base : base + 16384;
            int g = i & 1023;
            int row = g >> 3, c16 = g & 7;
            cp16(sb + off + SW128((uint32_t)row * 128 + c16 * 16),
                 src + ((size_t)(b * N_TOK) + m0 + row) * C_RED + c16 * 8);
        }
        CP_COMMIT();
    };

    // Residual prefetch: half0 -> channels [0,64) into stage2 (@81920),
    // half1 -> channels [64,128) into stage0 (@16384).  Plain 512B rows.
    auto issue_x = [&](int half) {
        const uint32_t base = half ? 16384u : 81920u;
        const float* src = x + ((size_t)(b * C_CH) + half * 64) * N_TOK + n0;
        for (int i = tid; i < 2048; i += 256) {
            int c = i >> 5, g = i & 31;
            cp16(sb + base + (uint32_t)c * 512 + g * 16,
                 src + (size_t)c * N_TOK + g * 4);
        }
        CP_COMMIT();
    };

    // prologue: Q (group 0), KV tiles 0 and 1 (groups 1, 2)
    {
        for (int i = tid; i < 1024; i += 256) {
            int row = i >> 3, c16 = i & 7;
            cp16(sb + SW128((uint32_t)row * 128 + c16 * 16),
                 g_q + ((size_t)(b * N_TOK) + n0 + row) * C_RED + c16 * 8);
        }
        CP_COMMIT();
        issue_kv(0);
        issue_kv(1);
    }

    // Convert Wp fp32 -> fp16 [c][64] 128B rows (SW128) into WP region.
    // LDG latency overlaps the cp.async waits below.
    #pragma unroll 4
    for (int g = tid; g < 2048; g += 256) {
        int c = g >> 3, c16 = g & 7;
        const float* s = Wp + c * C_RED + c16 * 8;
        float4 v0 = *(const float4*)s;
        float4 v1 = *(const float4*)(s + 4);
        uint4 u;
        u.x = packh(v0.x, v0.y);
        u.y = packh(v0.z, v0.w);
        u.z = packh(v1.x, v1.y);
        u.w = packh(v1.z, v1.w);
        *(uint4*)(smem + WP_OFF + SW128((uint32_t)c * 128 + c16 * 16)) = u;
    }

    uint32_t qf[4][4];
    float oacc[8][4] = {};
    float l0 = 0.0f, l1 = 0.0f;

    for (int kt = 0; kt < NKT; kt++) {
        CP_WAIT1();                // kv(kt) done; newest group may stay in flight
        __syncthreads();
        if (kt + 2 < NKT) issue_kv(kt + 2);
        else issue_x(kt + 2 - NKT);
        if (kt == 0) {
            uint32_t rowoff = (uint32_t)(w * 16 + rl) * 128 + cb;
            #pragma unroll
            for (int ks = 0; ks < 4; ks++)
                ldsm4(qf[ks], sb + SW128(rowoff + ks * 32));
        }
        const uint32_t SK = sb + 16384u + (uint32_t)(kt % 3) * 32768u;
        const uint32_t SV = SK + 16384;

        // ---- S = Q K^T, f16 accumulator (D = packed f16x2 pairs) ----
        uint32_t sd[16][2];
        #pragma unroll
        for (int t = 0; t < 16; t++) { sd[t][0] = 0u; sd[t][1] = 0u; }

        #pragma unroll
        for (int nb = 0; nb < 8; nb++) {
            uint32_t tokoff = (uint32_t)(nb * 16 + rl) * 128 + cb;
            #pragma unroll
            for (int ks = 0; ks < 4; ks++) {
                uint32_t kf[4];
                ldsm4(kf, SK + SW128(tokoff + ks * 32));
                mma_f16a(sd[2 * nb],     qf[ks], kf[0], kf[2]);
                mma_f16a(sd[2 * nb + 1], qf[ks], kf[1], kf[3]);
            }
        }

        // ---- fused softmax (f16x2 ex2 straight off the S regs) + PV ----
        __half2 hl0 = __float2half2_rn(0.0f);
        __half2 hl1 = __float2half2_rn(0.0f);
        #pragma unroll
        for (int j = 0; j < 8; j++) {
            uint32_t pf[4];
            pf[0] = exp2_h2(sd[2 * j][0]);
            pf[1] = exp2_h2(sd[2 * j][1]);
            pf[2] = exp2_h2(sd[2 * j + 1][0]);
            pf[3] = exp2_h2(sd[2 * j + 1][1]);
            hl0 = __hadd2(hl0, __hadd2(*(__half2*)&pf[0], *(__half2*)&pf[2]));
            hl1 = __hadd2(hl1, __hadd2(*(__half2*)&pf[1], *(__half2*)&pf[3]));

            uint32_t tokoff = (uint32_t)(j * 16 + rl) * 128 + cb;
            #pragma unroll
            for (int db = 0; db < 4; db++) {
                uint32_t vf[4];
                ldsm4t(vf, SV + SW128(tokoff + db * 32));
                mma_f16(oacc[2 * db],     pf, vf[0], vf[1]);
                mma_f16(oacc[2 * db + 1], pf, vf[2], vf[3]);
            }
        }
        float2 f0 = __half22float2(hl0);
        float2 f1 = __half22float2(hl1);
        l0 += f0.x + f0.y;
        l1 += f1.x + f1.y;
    }

    // ---- normalize O, stage as f16 into smem (reuse Q region) ----
    l0 += __shfl_xor_sync(0xffffffffu, l0, 1);
    l0 += __shfl_xor_sync(0xffffffffu, l0, 2);
    l1 += __shfl_xor_sync(0xffffffffu, l1, 1);
    l1 += __shfl_xor_sync(0xffffffffu, l1, 2);
    float i0 = 1.0f / l0, i1 = 1.0f / l1;

    {
        int lr = w * 16 + (lane >> 2);
        #pragma unroll
        for (int t = 0; t < 8; t++) {
            uint32_t cbyte = (uint32_t)(t * 8 + (lane & 3) * 2) * 2;
            *(uint32_t*)(smem + SW128((uint32_t)lr * 128 + cbyte)) =
                packh(oacc[t][0] * i0, oacc[t][1] * i0);
            *(uint32_t*)(smem + SW128((uint32_t)(lr + 8) * 128 + cbyte)) =
                packh(oacc[t][2] * i1, oacc[t][3] * i1);
        }
    }
    CP_WAIT0();          // residual x halves landed
    __syncthreads();

    // ---- projection: out[c][tok] = Wp[c][r] * O[tok][r] + x ----
    const int cg = w & 3, tg = w >> 2;
    float pacc[4][8][4] = {};
    #pragma unroll
    for (int ks = 0; ks < 4; ks++) {
        uint32_t awf[4][4];
        #pragma unroll
        for (int mt = 0; mt < 4; mt++)
            ldsm4(awf[mt], sb + WP_OFF +
                  SW128((uint32_t)(cg * 64 + mt * 16 + rl) * 128 + ks * 32 + cb));
        #pragma unroll
        for (int nb = 0; nb < 4; nb++) {
            uint32_t of[4];
            ldsm4(of, sb + SW128((uint32_t)(tg * 64 + nb * 16 + rl) * 128 + ks * 32 + cb));
            #pragma unroll
            for (int mt = 0; mt < 4; mt++) {
                mma_f16(pacc[mt][2 * nb],     awf[mt], of[0], of[2]);
                mma_f16(pacc[mt][2 * nb + 1], awf[mt], of[1], of[3]);
            }
        }
    }

    // ---- epilogue: residual add + store.  cg 0/1 -> x from smem, 2/3 -> LDG ----
    #pragma unroll
    for (int mt = 0; mt < 4; mt++) {
        int c = cg * 64 + mt * 16 + (lane >> 2);
        #pragma unroll
        for (int nt = 0; nt < 8; nt++) {
            int tl = tg * 64 + nt * 8 + (lane & 3) * 2;
            size_t gi = ((size_t)(b * C_CH + c)) * N_TOK + n0 + tl;
            float2 x0, x1;
            if (cg < 2) {
                uint32_t base = (c >> 6) ? 16384u : 81920u;
                x0 = *(float2*)(smem + base + (uint32_t)(c & 63) * 512 + tl * 4);
                x1 = *(float2*)(smem + base + (uint32_t)((c & 63) + 8) * 512 + tl * 4);
            } else {
                x0 = *(const float2*)(x + gi);
                x1 = *(const float2*)(x + gi + 8 * N_TOK);
            }
            *(float2*)(out + gi) =
                make_float2(pacc[mt][nt][0] + x0.x, pacc[mt][nt][1] + x0.y);
            *(float2*)(out + gi + 8 * N_TOK) =
                make_float2(pacc[mt][nt][2] + x1.x, pacc[mt][nt][3] + x1.y);
        }
    }
}

extern "C" void kernel_launch(void* const* d_in, const int* in_sizes, int n_in,
                              void* d_out, int out_size)
{
    const float* x  = (const float*)d_in[0];
    const float* Wq = (const float*)d_in[1];
    const float* Wk = (const float*)d_in[2];
    const float* Wv = (const float*)d_in[3];
    const float* Wp = (const float*)d_in[4];
    float* out = (float*)d_out;

    cudaFuncSetAttribute(qkv_tc_kernel,   cudaFuncAttributeMaxDynamicSharedMemorySize, QKV_SMEM);
    cudaFuncSetAttribute(attn_mma_kernel, cudaFuncAttributeMaxDynamicSharedMemorySize, ATTN_SMEM);

    qkv_tc_kernel  <<<dim3(N_TOK / 128, B_SZ), 384, QKV_SMEM>>>(x, Wq, Wk, Wv);
    attn_mma_kernel<<<dim3(N_TOK / 128, B_SZ), 256, ATTN_SMEM>>>(x, Wp, out);
}